// round 14
// baseline (speedup 1.0000x reference)
#include <cuda_runtime.h>

#define RES 128
#define NPTS_MAX 2097152

// ---------------- static scratch ----------------
__device__ float  d_params[6];
__device__ int    d_counter;
__device__ int    d_hist[NPTS_MAX];
__device__ int    d_bsumx[2048];
__device__ int    d_key[NPTS_MAX];
__device__ float4 d_pdata4[NPTS_MAX * 2];   // sorted: {gx,gy,gz,nx},{ny,nz,idx,0}

// ---------------- pass 1: zero histogram + setup ----------------
__global__ void k_zero(const float* __restrict__ aabb)
{
    long i = (long)blockIdx.x * blockDim.x + threadIdx.x;
    if (i * 4 < NPTS_MAX) {
        ((int4*)d_hist)[i] = make_int4(0, 0, 0, 0);
    }
    if (i == 0) {
        d_counter = 0;
        #pragma unroll
        for (int d = 0; d < 3; d++) {
            float amin = aabb[d], amax = aabb[d + 3];
            float s = 127.0f / (amax - amin);
            d_params[d]     = s;
            d_params[3 + d] = -amin * s;
        }
    }
}

// ---------------- pass 2: cell ids + histogram (2^21 fine bins) ----------------
__global__ void k_hist(const float* __restrict__ points, int n)
{
    int i = blockIdx.x * blockDim.x + threadIdx.x;
    if (i >= n) return;
    float sx = d_params[0], sy = d_params[1], sz = d_params[2];
    float ox = d_params[3], oy = d_params[4], oz = d_params[5];
    float gx = fminf(fmaxf(fmaf(points[3 * i + 0], sx, ox), 0.0f), 127.0f);
    float gy = fminf(fmaxf(fmaf(points[3 * i + 1], sy, oy), 0.0f), 127.0f);
    float gz = fminf(fmaxf(fmaf(points[3 * i + 2], sz, oz), 0.0f), 127.0f);
    int ix = min((int)gx, RES - 2);
    int iy = min((int)gy, RES - 2);
    int iz = min((int)gz, RES - 2);
    int key = (ix << 14) | (iy << 7) | iz;
    d_key[i] = key;
    atomicAdd(&d_hist[key], 1);
}

// ---------------- pass 3: per-1024-chunk scan + atomic chunk offset ----------------
__global__ void k_scan1()
{
    __shared__ int wsum[8];
    int tid = threadIdx.x;
    long base = (long)blockIdx.x * 1024 + tid * 4;
    int4 v = *(int4*)&d_hist[base];
    int t = v.x + v.y + v.z + v.w;
    int lane = tid & 31, wp = tid >> 5;
    int sc = t;
    #pragma unroll
    for (int off = 1; off < 32; off <<= 1) {
        int nv = __shfl_up_sync(0xffffffffu, sc, off);
        if (lane >= off) sc += nv;
    }
    if (lane == 31) wsum[wp] = sc;
    __syncthreads();
    if (tid < 8) {
        int ws = wsum[tid];
        #pragma unroll
        for (int off = 1; off < 8; off <<= 1) {
            int nv = __shfl_up_sync(0x000000ffu, ws, off);
            if (tid >= off) ws += nv;
        }
        wsum[tid] = ws;
    }
    __syncthreads();
    int excl = sc - t + (wp ? wsum[wp - 1] : 0);
    int4 o;
    o.x = excl; o.y = o.x + v.x; o.z = o.y + v.y; o.w = o.z + v.z;
    *(int4*)&d_hist[base] = o;
    if (tid == 255) {
        // disjoint chunk ranges; ordering permutes processing order only —
        // per-point output values are unchanged
        d_bsumx[blockIdx.x] = atomicAdd(&d_counter, excl + t);
    }
}

// ---------------- pass 4: scatter payloads into sorted order ----------------
__global__ void k_scatter(const float* __restrict__ points,
                          const float* __restrict__ normals, int n)
{
    int i = blockIdx.x * blockDim.x + threadIdx.x;
    if (i >= n) return;
    int key = d_key[i];
    int pos = atomicAdd(&d_hist[key], 1) + __ldg(&d_bsumx[key >> 10]);
    float sx = d_params[0], sy = d_params[1], sz = d_params[2];
    float ox = d_params[3], oy = d_params[4], oz = d_params[5];
    float4 A, B;
    A.x = fminf(fmaxf(fmaf(points[3 * i + 0], sx, ox), 0.0f), 127.0f);
    A.y = fminf(fmaxf(fmaf(points[3 * i + 1], sy, oy), 0.0f), 127.0f);
    A.z = fminf(fmaxf(fmaf(points[3 * i + 2], sz, oz), 0.0f), 127.0f);
    A.w = normals[3 * i + 0];
    B.x = normals[3 * i + 1]; B.y = normals[3 * i + 2];
    B.z = __int_as_float(i);  B.w = 0.0f;
    d_pdata4[(long)pos * 2 + 0] = A;
    d_pdata4[(long)pos * 2 + 1] = B;
}

// ---------------- main: 4 points/warp, 8 lanes/pt, convergent z-pair loads -------
// lane = 8p + u ; u = 4h + s. Per (dx,dy) round, 3 loads at zpair_base + 8t + u
// (128B per point per instruction). Lane's owned floats: F = 16j + 4s + q.
//   j-group sources: j0 <- h? (v1,w1):(v0,w0) ; j1 <- h? (v0,w0):(v2,w1) ;
//                    j2 <- h? (v2,w1):(v1,w0).
// Dot: comp[F/3] (4-way select on s), class (j+q)%3, channel (class+s)%3.
__global__ __launch_bounds__(256)
void k_main(const float* __restrict__ coeff, float* __restrict__ out, int n)
{
    const int lane = threadIdx.x & 31;
    const long wid = ((long)blockIdx.x * blockDim.x + threadIdx.x) >> 5;
    const int p = lane >> 3;        // point in warp 0..3
    const int u = lane & 7;
    const int s = u & 3;
    const bool h = (u & 4) != 0;

    long pi = wid * 4 + p;
    if (pi >= n) pi = n - 1;

    const float4 A4 = d_pdata4[pi * 2 + 0];
    const float4 B4 = d_pdata4[pi * 2 + 1];
    const float gx = A4.x, gy = A4.y, gz = A4.z;
    const float nx = A4.w, ny = B4.x, nz = B4.y;
    const int oidx = __float_as_int(B4.z);

    const int ix = min((int)gx, RES - 2);
    const int iy = min((int)gy, RES - 2);
    const int iz = min((int)gz, RES - 2);
    const float fx = gx - (float)ix;
    const float fy = gy - (float)iy;
    const float fz = gz - (float)iz;
    const float ex = 1.0f - fx, ey = 1.0f - fy, ez = 1.0f - fz;

    // f4 base of cell (ix,iy,iz); z-pair (dz=0,1) is 24 consecutive float4
    const long cell0 = (((long)ix * RES) + iy) * RES + iz;
    const float4* b4 = (const float4*)coeff + cell0 * 12 + u;

    float wv[12];
    #pragma unroll
    for (int k = 0; k < 12; k++) wv[k] = 0.0f;

    #pragma unroll
    for (int rd = 0; rd < 4; rd++) {
        const int dx = rd >> 1, dy = rd & 1;
        const float4* a = b4 + ((long)dx * (RES * RES * 12) + dy * (RES * 12));
        const float4 v0 = __ldg(a + 0);    // f4 [0,8)   of z-pair
        const float4 v1 = __ldg(a + 8);    // f4 [8,16)
        const float4 v2 = __ldg(a + 16);   // f4 [16,24)

        const float wxy = (dx ? fx : ex) * (dy ? fy : ey);
        const float w0 = wxy * ez;          // dz = 0
        const float w1 = wxy * fz;          // dz = 1

        const float wA = h ? w1 : w0;       // j0 and j2
        const float wB = h ? w0 : w1;       // j1
        const float4 vA = h ? v1 : v0;      // j0
        const float4 vB = h ? v0 : v2;      // j1
        const float4 vC = h ? v2 : v1;      // j2

        wv[0]  = fmaf(wA, vA.x, wv[0]);  wv[1]  = fmaf(wA, vA.y, wv[1]);
        wv[2]  = fmaf(wA, vA.z, wv[2]);  wv[3]  = fmaf(wA, vA.w, wv[3]);
        wv[4]  = fmaf(wB, vB.x, wv[4]);  wv[5]  = fmaf(wB, vB.y, wv[5]);
        wv[6]  = fmaf(wB, vB.z, wv[6]);  wv[7]  = fmaf(wB, vB.w, wv[7]);
        wv[8]  = fmaf(wA, vC.x, wv[8]);  wv[9]  = fmaf(wA, vC.y, wv[9]);
        wv[10] = fmaf(wA, vC.z, wv[10]); wv[11] = fmaf(wA, vC.w, wv[11]);
    }

    // SH components (degree 4), exact reference constants
    float comp[16];
    {
        const float x = nx, y = ny, z = nz;
        const float xx = x * x, yy = y * y, zz = z * z;
        const float xy = x * y, yz = y * z, xz = x * z;
        comp[0]  =  0.28209479177387814f;
        comp[1]  = -0.4886025119029199f * y;
        comp[2]  =  0.4886025119029199f * z;
        comp[3]  = -0.4886025119029199f * x;
        comp[4]  =  1.0925484305920792f * xy;
        comp[5]  = -1.0925484305920792f * yz;
        comp[6]  =  0.31539156525252005f * (2.0f * zz - xx - yy);
        comp[7]  = -1.0925484305920792f * xz;
        comp[8]  =  0.5462742152960396f * (xx - yy);
        comp[9]  = -0.5900435899266435f * y * (3.0f * xx - yy);
        comp[10] =  2.890611442640554f  * xy * z;
        comp[11] = -0.4570457994644658f * y * (4.0f * zz - xx - yy);
        comp[12] =  0.3731763325901154f * z * (2.0f * zz - 3.0f * xx - 3.0f * yy);
        comp[13] = -0.4570457994644658f * x * (4.0f * zz - xx - yy);
        comp[14] =  1.445305721320277f  * z * (xx - yy);
        comp[15] = -0.5900435899266435f * x * (xx - 3.0f * yy);
    }

    // class accumulation: F = 16j+4s+q ; comp F/3 ; class (j+q)%3
    float A0 = 0.0f, A1 = 0.0f, A2 = 0.0f;
    #pragma unroll
    for (int j = 0; j < 3; j++) {
        #pragma unroll
        for (int q = 0; q < 4; q++) {
            const int base = 16 * j + q;
            const float cc = (s == 0) ? comp[(base + 0)  / 3]
                            : (s == 1) ? comp[(base + 4)  / 3]
                            : (s == 2) ? comp[(base + 8)  / 3]
                                       : comp[(base + 12) / 3];
            const float val = wv[4 * j + q];
            const int c = (j + q) % 3;
            if (c == 0)      A0 = fmaf(cc, val, A0);
            else if (c == 1) A1 = fmaf(cc, val, A1);
            else             A2 = fmaf(cc, val, A2);
        }
    }

    // rotate: channel of A[c] is (c+s)%3 -> B[ch] = A[(ch-s) mod 3]
    float B0, B1, B2;
    if (s == 1)      { B0 = A2; B1 = A0; B2 = A1; }
    else if (s == 2) { B0 = A1; B1 = A2; B2 = A0; }
    else             { B0 = A0; B1 = A1; B2 = A2; }

    // reduce over the 8 lanes of this point (4 s-lanes x 2 h-halves)
    B0 += __shfl_xor_sync(0xffffffffu, B0, 1);
    B0 += __shfl_xor_sync(0xffffffffu, B0, 2);
    B0 += __shfl_xor_sync(0xffffffffu, B0, 4);
    B1 += __shfl_xor_sync(0xffffffffu, B1, 1);
    B1 += __shfl_xor_sync(0xffffffffu, B1, 2);
    B1 += __shfl_xor_sync(0xffffffffu, B1, 4);
    B2 += __shfl_xor_sync(0xffffffffu, B2, 1);
    B2 += __shfl_xor_sync(0xffffffffu, B2, 2);
    B2 += __shfl_xor_sync(0xffffffffu, B2, 4);

    if (u < 3) {
        float v = (u == 0) ? B0 : (u == 1) ? B1 : B2;
        out[3 * (long)oidx + u] = fmaxf(v, 0.0f);
    }
}

extern "C" void kernel_launch(void* const* d_in, const int* in_sizes, int n_in,
                              void* d_out, int out_size)
{
    const float* coeff   = (const float*)d_in[0];
    const float* aabb    = (const float*)d_in[1];
    const float* points  = (const float*)d_in[2];
    const float* normals = (const float*)d_in[3];
    float* out = (float*)d_out;

    int n = in_sizes[2] / 3;

    k_zero<<<NPTS_MAX / 4 / 256, 256>>>(aabb);
    k_hist<<<(n + 255) / 256, 256>>>(points, n);
    k_scan1<<<2048, 256>>>();
    k_scatter<<<(n + 255) / 256, 256>>>(points, normals, n);

    long warps = (n + 3) / 4;               // 4 points per warp
    long threads = warps * 32;
    int block = 256;
    long grid = (threads + block - 1) / block;
    k_main<<<(int)grid, block>>>(coeff, out, n);
}

// round 15
// speedup vs baseline: 1.4606x; 1.4606x over previous
#include <cuda_runtime.h>

#define RES 128
#define NPTS_MAX 2097152

// ---------------- static scratch ----------------
__device__ float  d_params[6];
__device__ int    d_counter;
__device__ int    d_hist[NPTS_MAX];
__device__ int    d_bsumx[2048];
__device__ int    d_key[NPTS_MAX];
__device__ float4 d_pdata4[NPTS_MAX * 2];   // sorted: {gx,gy,gz,nx},{ny,nz,idx,0}

// ---------------- pass 1: zero histogram + setup ----------------
__global__ void k_zero(const float* __restrict__ aabb)
{
    long i = (long)blockIdx.x * blockDim.x + threadIdx.x;
    if (i * 4 < NPTS_MAX) {
        ((int4*)d_hist)[i] = make_int4(0, 0, 0, 0);
    }
    if (i == 0) {
        d_counter = 0;
        #pragma unroll
        for (int d = 0; d < 3; d++) {
            float amin = aabb[d], amax = aabb[d + 3];
            float s = 127.0f / (amax - amin);
            d_params[d]     = s;
            d_params[3 + d] = -amin * s;
        }
    }
}

// ---------------- pass 2: cell ids + histogram (2^21 fine bins) ----------------
__global__ void k_hist(const float* __restrict__ points, int n)
{
    int i = blockIdx.x * blockDim.x + threadIdx.x;
    if (i >= n) return;
    float sx = d_params[0], sy = d_params[1], sz = d_params[2];
    float ox = d_params[3], oy = d_params[4], oz = d_params[5];
    float gx = fminf(fmaxf(fmaf(points[3 * i + 0], sx, ox), 0.0f), 127.0f);
    float gy = fminf(fmaxf(fmaf(points[3 * i + 1], sy, oy), 0.0f), 127.0f);
    float gz = fminf(fmaxf(fmaf(points[3 * i + 2], sz, oz), 0.0f), 127.0f);
    int ix = min((int)gx, RES - 2);
    int iy = min((int)gy, RES - 2);
    int iz = min((int)gz, RES - 2);
    int key = (ix << 14) | (iy << 7) | iz;
    d_key[i] = key;
    atomicAdd(&d_hist[key], 1);
}

// ---------------- pass 3: per-1024-chunk scan + atomic chunk offset ----------------
__global__ void k_scan1()
{
    __shared__ int wsum[8];
    int tid = threadIdx.x;
    long base = (long)blockIdx.x * 1024 + tid * 4;
    int4 v = *(int4*)&d_hist[base];
    int t = v.x + v.y + v.z + v.w;
    int lane = tid & 31, wp = tid >> 5;
    int sc = t;
    #pragma unroll
    for (int off = 1; off < 32; off <<= 1) {
        int nv = __shfl_up_sync(0xffffffffu, sc, off);
        if (lane >= off) sc += nv;
    }
    if (lane == 31) wsum[wp] = sc;
    __syncthreads();
    if (tid < 8) {
        int ws = wsum[tid];
        #pragma unroll
        for (int off = 1; off < 8; off <<= 1) {
            int nv = __shfl_up_sync(0x000000ffu, ws, off);
            if (tid >= off) ws += nv;
        }
        wsum[tid] = ws;
    }
    __syncthreads();
    int excl = sc - t + (wp ? wsum[wp - 1] : 0);
    int4 o;
    o.x = excl; o.y = o.x + v.x; o.z = o.y + v.y; o.w = o.z + v.z;
    *(int4*)&d_hist[base] = o;
    if (tid == 255) {
        // disjoint chunk ranges; ordering permutes processing order only —
        // per-point output values are unchanged (validated R12)
        d_bsumx[blockIdx.x] = atomicAdd(&d_counter, excl + t);
    }
}

// ---------------- pass 4: scatter payloads into sorted order ----------------
__global__ void k_scatter(const float* __restrict__ points,
                          const float* __restrict__ normals, int n)
{
    int i = blockIdx.x * blockDim.x + threadIdx.x;
    if (i >= n) return;
    int key = d_key[i];
    int pos = atomicAdd(&d_hist[key], 1) + __ldg(&d_bsumx[key >> 10]);
    float sx = d_params[0], sy = d_params[1], sz = d_params[2];
    float ox = d_params[3], oy = d_params[4], oz = d_params[5];
    float4 A, B;
    A.x = fminf(fmaxf(fmaf(points[3 * i + 0], sx, ox), 0.0f), 127.0f);
    A.y = fminf(fmaxf(fmaf(points[3 * i + 1], sy, oy), 0.0f), 127.0f);
    A.z = fminf(fmaxf(fmaf(points[3 * i + 2], sz, oz), 0.0f), 127.0f);
    A.w = normals[3 * i + 0];
    B.x = normals[3 * i + 1]; B.y = normals[3 * i + 2];
    B.z = __int_as_float(i);  B.w = 0.0f;
    d_pdata4[(long)pos * 2 + 0] = A;
    d_pdata4[(long)pos * 2 + 1] = B;
}

// ---------------- main: 8 points/warp, interleaved loads + class rotation ----------
// lane = 4p + s. reg j (0..2), comp q (0..3) <-> cell float F = 16j+4s+q.
//   comp index = F/3 (per-lane select), channel = (class + s)%3, class = (j+q)%3.
__global__ __launch_bounds__(256)
void k_main(const float* __restrict__ coeff, float* __restrict__ out, int n)
{
    const int lane = threadIdx.x & 31;
    const long wid = ((long)blockIdx.x * blockDim.x + threadIdx.x) >> 5;
    const int p = lane >> 2;
    const int s = lane & 3;

    long pi = wid * 8 + p;
    if (pi >= n) pi = n - 1;

    const float4 A4 = d_pdata4[pi * 2 + 0];
    const float4 B4 = d_pdata4[pi * 2 + 1];
    const float gx = A4.x, gy = A4.y, gz = A4.z;
    const float nx = A4.w, ny = B4.x, nz = B4.y;
    const int oidx = __float_as_int(B4.z);

    const int ix = min((int)gx, RES - 2);
    const int iy = min((int)gy, RES - 2);
    const int iz = min((int)gz, RES - 2);
    const float fx = gx - (float)ix;
    const float fy = gy - (float)iy;
    const float fz = gz - (float)iz;
    const float ex = 1.0f - fx, ey = 1.0f - fy, ez = 1.0f - fz;

    const long cell0 = (((long)ix * RES) + iy) * RES + iz;
    const float4* b4 = (const float4*)(coeff + cell0 * 48) + s;

    float wv[12];
    #pragma unroll
    for (int k = 0; k < 12; k++) wv[k] = 0.0f;

    #pragma unroll
    for (int rd = 0; rd < 8; rd++) {
        const int dx = (rd >> 2) & 1, dy = (rd >> 1) & 1, dz = rd & 1;
        const float4* c4 = b4 + (dx * (RES * RES * 12) + dy * (RES * 12) + dz * 12);
        float4 v0 = __ldg(c4 + 0);
        float4 v1 = __ldg(c4 + 4);
        float4 v2 = __ldg(c4 + 8);
        const float w = (dx ? fx : ex) * (dy ? fy : ey) * (dz ? fz : ez);
        wv[0]  = fmaf(w, v0.x, wv[0]);  wv[1]  = fmaf(w, v0.y, wv[1]);
        wv[2]  = fmaf(w, v0.z, wv[2]);  wv[3]  = fmaf(w, v0.w, wv[3]);
        wv[4]  = fmaf(w, v1.x, wv[4]);  wv[5]  = fmaf(w, v1.y, wv[5]);
        wv[6]  = fmaf(w, v1.z, wv[6]);  wv[7]  = fmaf(w, v1.w, wv[7]);
        wv[8]  = fmaf(w, v2.x, wv[8]);  wv[9]  = fmaf(w, v2.y, wv[9]);
        wv[10] = fmaf(w, v2.z, wv[10]); wv[11] = fmaf(w, v2.w, wv[11]);
    }

    float comp[16];
    {
        const float x = nx, y = ny, z = nz;
        const float xx = x * x, yy = y * y, zz = z * z;
        const float xy = x * y, yz = y * z, xz = x * z;
        comp[0]  =  0.28209479177387814f;
        comp[1]  = -0.4886025119029199f * y;
        comp[2]  =  0.4886025119029199f * z;
        comp[3]  = -0.4886025119029199f * x;
        comp[4]  =  1.0925484305920792f * xy;
        comp[5]  = -1.0925484305920792f * yz;
        comp[6]  =  0.31539156525252005f * (2.0f * zz - xx - yy);
        comp[7]  = -1.0925484305920792f * xz;
        comp[8]  =  0.5462742152960396f * (xx - yy);
        comp[9]  = -0.5900435899266435f * y * (3.0f * xx - yy);
        comp[10] =  2.890611442640554f  * xy * z;
        comp[11] = -0.4570457994644658f * y * (4.0f * zz - xx - yy);
        comp[12] =  0.3731763325901154f * z * (2.0f * zz - 3.0f * xx - 3.0f * yy);
        comp[13] = -0.4570457994644658f * x * (4.0f * zz - xx - yy);
        comp[14] =  1.445305721320277f  * z * (xx - yy);
        comp[15] = -0.5900435899266435f * x * (xx - 3.0f * yy);
    }

    float A0 = 0.0f, A1 = 0.0f, A2 = 0.0f;
    #pragma unroll
    for (int j = 0; j < 3; j++) {
        #pragma unroll
        for (int q = 0; q < 4; q++) {
            const int base = 16 * j + q;
            const float cc = (s == 0) ? comp[(base + 0)  / 3]
                            : (s == 1) ? comp[(base + 4)  / 3]
                            : (s == 2) ? comp[(base + 8)  / 3]
                                       : comp[(base + 12) / 3];
            const float val = wv[4 * j + q];
            const int c = (j + q) % 3;
            if (c == 0)      A0 = fmaf(cc, val, A0);
            else if (c == 1) A1 = fmaf(cc, val, A1);
            else             A2 = fmaf(cc, val, A2);
        }
    }

    float B0, B1, B2;
    if (s == 1)      { B0 = A2; B1 = A0; B2 = A1; }
    else if (s == 2) { B0 = A1; B1 = A2; B2 = A0; }
    else             { B0 = A0; B1 = A1; B2 = A2; }

    B0 += __shfl_xor_sync(0xffffffffu, B0, 1);
    B0 += __shfl_xor_sync(0xffffffffu, B0, 2);
    B1 += __shfl_xor_sync(0xffffffffu, B1, 1);
    B1 += __shfl_xor_sync(0xffffffffu, B1, 2);
    B2 += __shfl_xor_sync(0xffffffffu, B2, 1);
    B2 += __shfl_xor_sync(0xffffffffu, B2, 2);

    if (s < 3) {
        float v = (s == 0) ? B0 : (s == 1) ? B1 : B2;
        out[3 * (long)oidx + s] = fmaxf(v, 0.0f);
    }
}

extern "C" void kernel_launch(void* const* d_in, const int* in_sizes, int n_in,
                              void* d_out, int out_size)
{
    const float* coeff   = (const float*)d_in[0];
    const float* aabb    = (const float*)d_in[1];
    const float* points  = (const float*)d_in[2];
    const float* normals = (const float*)d_in[3];
    float* out = (float*)d_out;

    int n = in_sizes[2] / 3;

    k_zero<<<NPTS_MAX / 4 / 256, 256>>>(aabb);
    k_hist<<<(n + 255) / 256, 256>>>(points, n);
    k_scan1<<<2048, 256>>>();
    k_scatter<<<(n + 255) / 256, 256>>>(points, normals, n);

    long warps = (n + 7) / 8;
    long threads = warps * 32;
    int block = 256;
    long grid = (threads + block - 1) / block;
    k_main<<<(int)grid, block>>>(coeff, out, n);
}

// round 16
// speedup vs baseline: 1.5671x; 1.0729x over previous
#include <cuda_runtime.h>

#define RES 128
#define NPTS_MAX 2097152

// ---------------- static scratch ----------------
__device__ float  d_params[6];
__device__ int    d_hist[NPTS_MAX];
__device__ int    d_btot[2048];
__device__ int    d_bsumx[2048];
__device__ float4 d_pdata4[NPTS_MAX * 2];   // sorted: {gx,gy,gz,nx},{ny,nz,idx,0}

// ---------------- pass 1: zero histogram + setup ----------------
__global__ void k_zero(const float* __restrict__ aabb)
{
    long i = (long)blockIdx.x * blockDim.x + threadIdx.x;
    if (i * 4 < NPTS_MAX) {
        ((int4*)d_hist)[i] = make_int4(0, 0, 0, 0);
    }
    if (i == 0) {
        #pragma unroll
        for (int d = 0; d < 3; d++) {
            float amin = aabb[d], amax = aabb[d + 3];
            float s = 127.0f / (amax - amin);
            d_params[d]     = s;
            d_params[3 + d] = -amin * s;
        }
    }
}

__device__ __forceinline__ int cell_key(float gx, float gy, float gz)
{
    int ix = min((int)gx, RES - 2);
    int iy = min((int)gy, RES - 2);
    int iz = min((int)gz, RES - 2);
    return (ix << 14) | (iy << 7) | iz;
}

// ---------------- pass 2: histogram (2^21 fine bins, key recomputed later) -------
__global__ void k_hist(const float* __restrict__ points, int n)
{
    int i = blockIdx.x * blockDim.x + threadIdx.x;
    if (i >= n) return;
    float sx = d_params[0], sy = d_params[1], sz = d_params[2];
    float ox = d_params[3], oy = d_params[4], oz = d_params[5];
    float gx = fminf(fmaxf(fmaf(points[3 * i + 0], sx, ox), 0.0f), 127.0f);
    float gy = fminf(fmaxf(fmaf(points[3 * i + 1], sy, oy), 0.0f), 127.0f);
    float gz = fminf(fmaxf(fmaf(points[3 * i + 2], sz, oz), 0.0f), 127.0f);
    atomicAdd(&d_hist[cell_key(gx, gy, gz)], 1);
}

// ---------------- pass 3: per-1024-chunk exclusive scan ----------------
__global__ void k_scan1()
{
    __shared__ int wsum[8];
    int tid = threadIdx.x;
    long base = (long)blockIdx.x * 1024 + tid * 4;
    int4 v = *(int4*)&d_hist[base];
    int t = v.x + v.y + v.z + v.w;
    int lane = tid & 31, wp = tid >> 5;
    int sc = t;
    #pragma unroll
    for (int off = 1; off < 32; off <<= 1) {
        int nv = __shfl_up_sync(0xffffffffu, sc, off);
        if (lane >= off) sc += nv;
    }
    if (lane == 31) wsum[wp] = sc;
    __syncthreads();
    if (tid < 8) {
        int ws = wsum[tid];
        #pragma unroll
        for (int off = 1; off < 8; off <<= 1) {
            int nv = __shfl_up_sync(0x000000ffu, ws, off);
            if (tid >= off) ws += nv;
        }
        wsum[tid] = ws;
    }
    __syncthreads();
    int excl = sc - t + (wp ? wsum[wp - 1] : 0);
    int4 o;
    o.x = excl; o.y = o.x + v.x; o.z = o.y + v.y; o.w = o.z + v.z;
    *(int4*)&d_hist[base] = o;
    if (tid == 255) d_btot[blockIdx.x] = excl + t;
}

// ---------------- pass 4: deterministic scan of the 2048 chunk totals -----------
// (global x-major placement -> concurrent k_main blocks share coeff L2 footprint)
__global__ void k_scan2()
{
    __shared__ int wsum[8];
    int tid = threadIdx.x;
    int base = tid * 8;
    int v[8]; int t = 0;
    #pragma unroll
    for (int k = 0; k < 8; k++) { v[k] = d_btot[base + k]; t += v[k]; }
    int lane = tid & 31, wp = tid >> 5;
    int sc = t;
    #pragma unroll
    for (int off = 1; off < 32; off <<= 1) {
        int nv = __shfl_up_sync(0xffffffffu, sc, off);
        if (lane >= off) sc += nv;
    }
    if (lane == 31) wsum[wp] = sc;
    __syncthreads();
    if (tid < 8) {
        int ws = wsum[tid];
        #pragma unroll
        for (int off = 1; off < 8; off <<= 1) {
            int nv = __shfl_up_sync(0x000000ffu, ws, off);
            if (tid >= off) ws += nv;
        }
        wsum[tid] = ws;
    }
    __syncthreads();
    int run = sc - t + (wp ? wsum[wp - 1] : 0);
    #pragma unroll
    for (int k = 0; k < 8; k++) { d_bsumx[base + k] = run; run += v[k]; }
}

// ---------------- pass 5: scatter payloads into sorted order ----------------
__global__ void k_scatter(const float* __restrict__ points,
                          const float* __restrict__ normals, int n)
{
    int i = blockIdx.x * blockDim.x + threadIdx.x;
    if (i >= n) return;
    float sx = d_params[0], sy = d_params[1], sz = d_params[2];
    float ox = d_params[3], oy = d_params[4], oz = d_params[5];
    float4 A, B;
    A.x = fminf(fmaxf(fmaf(points[3 * i + 0], sx, ox), 0.0f), 127.0f);
    A.y = fminf(fmaxf(fmaf(points[3 * i + 1], sy, oy), 0.0f), 127.0f);
    A.z = fminf(fmaxf(fmaf(points[3 * i + 2], sz, oz), 0.0f), 127.0f);
    A.w = normals[3 * i + 0];
    B.x = normals[3 * i + 1]; B.y = normals[3 * i + 2];
    B.z = __int_as_float(i);  B.w = 0.0f;
    int key = cell_key(A.x, A.y, A.z);
    int pos = atomicAdd(&d_hist[key], 1) + __ldg(&d_bsumx[key >> 10]);
    d_pdata4[(long)pos * 2 + 0] = A;
    d_pdata4[(long)pos * 2 + 1] = B;
}

// ---------------- main: 8 points/warp, interleaved loads + class rotation ----------
// lane = 4p + s. reg j (0..2), comp q (0..3) <-> cell float F = 16j+4s+q.
//   comp index = F/3 (per-lane select), channel = (class + s)%3, class = (j+q)%3.
__global__ __launch_bounds__(256)
void k_main(const float* __restrict__ coeff, float* __restrict__ out, int n)
{
    const int lane = threadIdx.x & 31;
    const long wid = ((long)blockIdx.x * blockDim.x + threadIdx.x) >> 5;
    const int p = lane >> 2;
    const int s = lane & 3;

    long pi = wid * 8 + p;
    if (pi >= n) pi = n - 1;

    const float4 A4 = d_pdata4[pi * 2 + 0];
    const float4 B4 = d_pdata4[pi * 2 + 1];
    const float gx = A4.x, gy = A4.y, gz = A4.z;
    const float nx = A4.w, ny = B4.x, nz = B4.y;
    const int oidx = __float_as_int(B4.z);

    const int ix = min((int)gx, RES - 2);
    const int iy = min((int)gy, RES - 2);
    const int iz = min((int)gz, RES - 2);
    const float fx = gx - (float)ix;
    const float fy = gy - (float)iy;
    const float fz = gz - (float)iz;
    const float ex = 1.0f - fx, ey = 1.0f - fy, ez = 1.0f - fz;

    const long cell0 = (((long)ix * RES) + iy) * RES + iz;
    const float4* b4 = (const float4*)(coeff + cell0 * 48) + s;

    float wv[12];
    #pragma unroll
    for (int k = 0; k < 12; k++) wv[k] = 0.0f;

    #pragma unroll
    for (int rd = 0; rd < 8; rd++) {
        const int dx = (rd >> 2) & 1, dy = (rd >> 1) & 1, dz = rd & 1;
        const float4* c4 = b4 + (dx * (RES * RES * 12) + dy * (RES * 12) + dz * 12);
        float4 v0 = __ldg(c4 + 0);
        float4 v1 = __ldg(c4 + 4);
        float4 v2 = __ldg(c4 + 8);
        const float w = (dx ? fx : ex) * (dy ? fy : ey) * (dz ? fz : ez);
        wv[0]  = fmaf(w, v0.x, wv[0]);  wv[1]  = fmaf(w, v0.y, wv[1]);
        wv[2]  = fmaf(w, v0.z, wv[2]);  wv[3]  = fmaf(w, v0.w, wv[3]);
        wv[4]  = fmaf(w, v1.x, wv[4]);  wv[5]  = fmaf(w, v1.y, wv[5]);
        wv[6]  = fmaf(w, v1.z, wv[6]);  wv[7]  = fmaf(w, v1.w, wv[7]);
        wv[8]  = fmaf(w, v2.x, wv[8]);  wv[9]  = fmaf(w, v2.y, wv[9]);
        wv[10] = fmaf(w, v2.z, wv[10]); wv[11] = fmaf(w, v2.w, wv[11]);
    }

    float comp[16];
    {
        const float x = nx, y = ny, z = nz;
        const float xx = x * x, yy = y * y, zz = z * z;
        const float xy = x * y, yz = y * z, xz = x * z;
        comp[0]  =  0.28209479177387814f;
        comp[1]  = -0.4886025119029199f * y;
        comp[2]  =  0.4886025119029199f * z;
        comp[3]  = -0.4886025119029199f * x;
        comp[4]  =  1.0925484305920792f * xy;
        comp[5]  = -1.0925484305920792f * yz;
        comp[6]  =  0.31539156525252005f * (2.0f * zz - xx - yy);
        comp[7]  = -1.0925484305920792f * xz;
        comp[8]  =  0.5462742152960396f * (xx - yy);
        comp[9]  = -0.5900435899266435f * y * (3.0f * xx - yy);
        comp[10] =  2.890611442640554f  * xy * z;
        comp[11] = -0.4570457994644658f * y * (4.0f * zz - xx - yy);
        comp[12] =  0.3731763325901154f * z * (2.0f * zz - 3.0f * xx - 3.0f * yy);
        comp[13] = -0.4570457994644658f * x * (4.0f * zz - xx - yy);
        comp[14] =  1.445305721320277f  * z * (xx - yy);
        comp[15] = -0.5900435899266435f * x * (xx - 3.0f * yy);
    }

    float A0 = 0.0f, A1 = 0.0f, A2 = 0.0f;
    #pragma unroll
    for (int j = 0; j < 3; j++) {
        #pragma unroll
        for (int q = 0; q < 4; q++) {
            const int base = 16 * j + q;
            const float cc = (s == 0) ? comp[(base + 0)  / 3]
                            : (s == 1) ? comp[(base + 4)  / 3]
                            : (s == 2) ? comp[(base + 8)  / 3]
                                       : comp[(base + 12) / 3];
            const float val = wv[4 * j + q];
            const int c = (j + q) % 3;
            if (c == 0)      A0 = fmaf(cc, val, A0);
            else if (c == 1) A1 = fmaf(cc, val, A1);
            else             A2 = fmaf(cc, val, A2);
        }
    }

    float B0, B1, B2;
    if (s == 1)      { B0 = A2; B1 = A0; B2 = A1; }
    else if (s == 2) { B0 = A1; B1 = A2; B2 = A0; }
    else             { B0 = A0; B1 = A1; B2 = A2; }

    B0 += __shfl_xor_sync(0xffffffffu, B0, 1);
    B0 += __shfl_xor_sync(0xffffffffu, B0, 2);
    B1 += __shfl_xor_sync(0xffffffffu, B1, 1);
    B1 += __shfl_xor_sync(0xffffffffu, B1, 2);
    B2 += __shfl_xor_sync(0xffffffffu, B2, 1);
    B2 += __shfl_xor_sync(0xffffffffu, B2, 2);

    if (s < 3) {
        float v = (s == 0) ? B0 : (s == 1) ? B1 : B2;
        __stcs(&out[3 * (long)oidx + s], fmaxf(v, 0.0f));   // streaming store: don't pollute L2
    }
}

extern "C" void kernel_launch(void* const* d_in, const int* in_sizes, int n_in,
                              void* d_out, int out_size)
{
    const float* coeff   = (const float*)d_in[0];
    const float* aabb    = (const float*)d_in[1];
    const float* points  = (const float*)d_in[2];
    const float* normals = (const float*)d_in[3];
    float* out = (float*)d_out;

    int n = in_sizes[2] / 3;

    k_zero<<<NPTS_MAX / 4 / 256, 256>>>(aabb);
    k_hist<<<(n + 255) / 256, 256>>>(points, n);
    k_scan1<<<2048, 256>>>();
    k_scan2<<<1, 256>>>();
    k_scatter<<<(n + 255) / 256, 256>>>(points, normals, n);

    long warps = (n + 7) / 8;
    long threads = warps * 32;
    int block = 256;
    long grid = (threads + block - 1) / block;
    k_main<<<(int)grid, block>>>(coeff, out, n);
}